// round 11
// baseline (speedup 1.0000x reference)
#include <cuda_runtime.h>
#include <cuda_bf16.h>

#define B_DIM 128
#define N_DIM 256
#define RSW   132                  // P row stride in words: even, %4==0 -> LDS.128 rows
#define ITERS 50
#define NTHR  1024

// ---- smem word offsets ----
#define W_PH   0                       // 33792 : P bf16 padded rows (256 x 132)
#define W_S    33792
#define W_BM   34048
#define W_GA   34304
#define W_U    34560
#define W_V    34816
#define W_W    35072
#define W_SP   35328                   // 4096 : 16 x 256 column partials
#define W_RP   39424                   // 1024 : 4 x 256 row partials
#define W_RED  40448                   // 64
#define W_EI   40512                   // 256
#define W_PW   40768                   // 8*256 : r^k tables
#define W_AN   42816                   // 32*256 : anchor rows
#define SMEM_WORDS (W_AN + 32*256)     // 51008 words = 204032 B

__device__ float    g_sum = 0.f;
__device__ int      g_cnt = 0;
__device__ unsigned g_tk  = 0u;

__device__ __forceinline__ float bf_lo(unsigned w) { return __int_as_float(w << 16); }
__device__ __forceinline__ float bf_hi(unsigned w) { return __int_as_float(w & 0xffff0000u); }

// ------------------------------------------------------------- mega kernel ---
__global__ void __launch_bounds__(NTHR, 1)
mega_kernel(const float* __restrict__ yp, const int* __restrict__ ytr,
            float* __restrict__ out) {
    extern __shared__ unsigned smw[];
    unsigned* Pw = smw + W_PH;
    float* s   = (float*)(smw + W_S);
    float* Bm  = (float*)(smw + W_BM);
    float* gA  = (float*)(smw + W_GA);
    float* u   = (float*)(smw + W_U);
    float* v   = (float*)(smw + W_V);
    float* w   = (float*)(smw + W_W);
    float* sp  = (float*)(smw + W_SP);
    float* rp  = (float*)(smw + W_RP);
    float* red = (float*)(smw + W_RED);
    int*   ei  = (int*)(smw + W_EI);
    float* pw  = (float*)(smw + W_PW);
    float* AN  = (float*)(smw + W_AN);

    const int tid  = threadIdx.x;
    const int b    = blockIdx.x;
    const int lane = tid & 31;
    const int wid  = tid >> 5;

    // ---- fused global min/max of y_true (L2-hot scan) ----
    int shift;
    {
        const int4* t4 = (const int4*)ytr;
        unsigned umx = 0u, umn = 0u;
        #pragma unroll
        for (int k = 0; k < (B_DIM * N_DIM / 4) / NTHR; k++) {
            int4 x = t4[tid + k * NTHR];
            unsigned u0 = (unsigned)x.x ^ 0x80000000u;
            unsigned u1 = (unsigned)x.y ^ 0x80000000u;
            unsigned u2 = (unsigned)x.z ^ 0x80000000u;
            unsigned u3 = (unsigned)x.w ^ 0x80000000u;
            umx = max(umx, max(max(u0, u1), max(u2, u3)));
            umn = max(umn, max(max(~u0, ~u1), max(~u2, ~u3)));
        }
        for (int o = 16; o; o >>= 1) {
            umx = max(umx, __shfl_xor_sync(0xffffffffu, umx, o));
            umn = max(umn, __shfl_xor_sync(0xffffffffu, umn, o));
        }
        unsigned* ur = (unsigned*)red;
        if (lane == 0) { ur[wid] = umx; ur[32 + wid] = umn; }
        __syncthreads();
        if (tid == 0) {
            for (int k = 1; k < 32; k++) { umx = max(umx, ur[k]); umn = max(umn, ur[32 + k]); }
            red[63] = __int_as_float((int)(umx ^ 0x80000000u) + (int)((~umn) ^ 0x80000000u));
        }
        __syncthreads();
        shift = __float_as_int(red[63]);
    }

    // ---- setup: scores, flipped relevancy, gains ----
    float sj = 0.f, gain = 0.f; int e = 0;
    if (tid < 256) {
        sj = yp[b * N_DIM + tid];
        s[tid] = sj;
        e = shift - ytr[b * N_DIM + tid];
        e = min(max(e, 0), 30);
        ei[tid] = e;
        gain = (float)((1u << e) - 1u);
        gA[tid] = gain;
        u[tid] = 1.0f;
    }
    __syncthreads();

    // ---- B_mat (Kahan) + IDCG via stable rank (threads 0..255) ----
    float idcg = 0.f;
    if (tid < 256) {
        float bsum = 0.f, bc = 0.f;
        int pos = 0;
        for (int k = 0; k < N_DIM; k++) {
            float d  = fabsf(sj - s[k]);
            float y  = d - bc;
            float t2 = bsum + y;
            bc = (t2 - bsum) - y;
            bsum = t2;
            int ek = ei[k];
            pos += (ek > e) ? 1 : 0;
            pos += ((k < tid) && (ek == e)) ? 1 : 0;
        }
        Bm[tid] = bsum;
        float x = gain / log2f((float)(pos + 2));
        for (int o = 16; o; o >>= 1) x += __shfl_xor_sync(0xffffffffu, x, o);
        if (lane == 0) red[wid] = x;
    }
    __syncthreads();
    if (tid == 0) { for (int k = 0; k < 8; k++) idcg += red[k]; }

    // ==== P build (exp-free block scheme) ====
    // r^k tables, k=0..7
    if (tid < 256) {
        float r = __expf(-2.0f * sj);
        float pk = 1.0f;
        pw[tid] = 1.0f;
        #pragma unroll
        for (int k = 1; k < 8; k++) { pk *= r; pw[k * 256 + tid] = pk; }
    }
    // anchors: 32 warps -> warp wid computes row 8*wid
    {
        int m = wid;
        float sc = (float)(255 - 16 * m);
        float lg[8];
        float mxl = -3.4e38f;
        #pragma unroll
        for (int c = 0; c < 8; c++) {
            int j = c * 32 + lane;
            lg[c] = fmaf(s[j], sc, -Bm[j]);
            mxl = fmaxf(mxl, lg[c]);
        }
        for (int o = 16; o; o >>= 1) mxl = fmaxf(mxl, __shfl_xor_sync(0xffffffffu, mxl, o));
        float* an = AN + m * 256;
        #pragma unroll
        for (int c = 0; c < 8; c++) an[c * 32 + lane] = __expf(lg[c] - mxl);
    }
    __syncthreads();

    // fill: warp per row, 8 rows per warp
    #pragma unroll 1
    for (int t = 0; t < 8; t++) {
        int i = wid + 32 * t;
        const float* an = AN + (i >> 3) * 256;
        const float* pk = pw + (i & 7) * 256;
        float f0[4], f1[4];
        float ssum = 0.f;
        #pragma unroll
        for (int c = 0; c < 4; c++) {
            float2 a2 = *(const float2*)(an + c * 64 + 2 * lane);
            float2 k2 = *(const float2*)(pk + c * 64 + 2 * lane);
            f0[c] = a2.x * k2.x;
            f1[c] = a2.y * k2.y;
            ssum += f0[c] + f1[c];
        }
        for (int o = 16; o; o >>= 1) ssum += __shfl_xor_sync(0xffffffffu, ssum, o);
        float inv = 1.0f / ssum;
        unsigned* row = Pw + (unsigned)i * RSW;
        #pragma unroll
        for (int c = 0; c < 4; c++) {
            __nv_bfloat162 pr = __floats2bfloat162_rn(f0[c] * inv, f1[c] * inv);
            row[c * 32 + lane] = *(unsigned*)&pr;
        }
    }
    __syncthreads();

    // ---- Sinkhorn with early exit ----
    const int quad = tid & 63;                       // column quad (cols 4q..4q+3)
    const int grp  = tid >> 6;                       // row group (16 rows), 16 groups
    const unsigned* colp = Pw + (unsigned)(grp * 16) * RSW + 2 * quad;
    const float* uo = u + grp * 16;
    const int ir = tid & 255;                        // row for row pass
    const int qq = tid >> 8;                         // column quarter (64 cols)
    const unsigned* rowp = Pw + (unsigned)ir * RSW + (unsigned)(qq * 32);
    const float* vh = v + qq * 64;
    float vprev = 0.f;

    for (int it = 0; it < ITERS; it++) {
        // column pass: partial over 16 rows for cols 4quad..4quad+3 (LDS.64 on P)
        float a0 = 0.f, a1 = 0.f, a2 = 0.f, a3 = 0.f;
        #pragma unroll
        for (int ri = 0; ri < 4; ri++) {
            float4 uu = *(const float4*)(uo + 4 * ri);
            uint2 w0 = *(const uint2*)(colp + (4 * ri + 0) * RSW);
            uint2 w1 = *(const uint2*)(colp + (4 * ri + 1) * RSW);
            uint2 w2 = *(const uint2*)(colp + (4 * ri + 2) * RSW);
            uint2 w3 = *(const uint2*)(colp + (4 * ri + 3) * RSW);
            a0 = fmaf(bf_lo(w0.x), uu.x, a0); a1 = fmaf(bf_hi(w0.x), uu.x, a1);
            a2 = fmaf(bf_lo(w0.y), uu.x, a2); a3 = fmaf(bf_hi(w0.y), uu.x, a3);
            a0 = fmaf(bf_lo(w1.x), uu.y, a0); a1 = fmaf(bf_hi(w1.x), uu.y, a1);
            a2 = fmaf(bf_lo(w1.y), uu.y, a2); a3 = fmaf(bf_hi(w1.y), uu.y, a3);
            a0 = fmaf(bf_lo(w2.x), uu.z, a0); a1 = fmaf(bf_hi(w2.x), uu.z, a1);
            a2 = fmaf(bf_lo(w2.y), uu.z, a2); a3 = fmaf(bf_hi(w2.y), uu.z, a3);
            a0 = fmaf(bf_lo(w3.x), uu.w, a0); a1 = fmaf(bf_hi(w3.x), uu.w, a1);
            a2 = fmaf(bf_lo(w3.y), uu.w, a2); a3 = fmaf(bf_hi(w3.y), uu.w, a3);
        }
        *(float4*)(sp + grp * 256 + 4 * quad) = make_float4(a0, a1, a2, a3);
        __syncthreads();

        // v update + convergence flag (threads 0..255)
        int ch = 0;
        if (tid < 256) {
            float s0 = (sp[tid]        + sp[256 + tid])  + (sp[512 + tid]  + sp[768 + tid]);
            float s1 = (sp[1024 + tid] + sp[1280 + tid]) + (sp[1536 + tid] + sp[1792 + tid]);
            float s2 = (sp[2048 + tid] + sp[2304 + tid]) + (sp[2560 + tid] + sp[2816 + tid]);
            float s3 = (sp[3072 + tid] + sp[3328 + tid]) + (sp[3584 + tid] + sp[3840 + tid]);
            float S = (s0 + s1) + (s2 + s3);
            float vn = 1.0f / fmaxf(S, 1e-10f);
            v[tid] = vn;
            ch = (fabsf(vn - vprev) > 1e-4f * fabsf(vprev)) ? 1 : 0;
            vprev = vn;
        }
        if (__syncthreads_or(ch) == 0) break;

        // row pass: quarter-row dot with v (LDS.128 on P)
        float r0 = 0.f, r1 = 0.f, r2 = 0.f, r3 = 0.f;
        #pragma unroll
        for (int j4 = 0; j4 < 8; j4++) {
            float4 v0 = *(const float4*)(vh + 8 * j4);
            float4 v1 = *(const float4*)(vh + 8 * j4 + 4);
            uint4 pq = *(const uint4*)(rowp + 4 * j4);
            r0 = fmaf(bf_lo(pq.x), v0.x, r0); r1 = fmaf(bf_hi(pq.x), v0.y, r1);
            r2 = fmaf(bf_lo(pq.y), v0.z, r2); r3 = fmaf(bf_hi(pq.y), v0.w, r3);
            r0 = fmaf(bf_lo(pq.z), v1.x, r0); r1 = fmaf(bf_hi(pq.z), v1.y, r1);
            r2 = fmaf(bf_lo(pq.w), v1.z, r2); r3 = fmaf(bf_hi(pq.w), v1.w, r3);
        }
        rp[qq * 256 + ir] = (r0 + r1) + (r2 + r3);
        __syncthreads();

        if (tid < 256)
            u[tid] = 1.0f / fmaxf((rp[tid] + rp[256 + tid]) + (rp[512 + tid] + rp[768 + tid]), 1e-10f);
        __syncthreads();
    }

    // ---- final: num = sum_i disc_i * u_i * (P[i] . (v*g)) ----
    if (tid < 256) w[tid] = v[tid] * gA[tid];
    __syncthreads();
    {
        float r0 = 0.f, r1 = 0.f, r2 = 0.f, r3 = 0.f;
        const float* wh = w + qq * 64;
        #pragma unroll
        for (int j4 = 0; j4 < 8; j4++) {
            float4 v0 = *(const float4*)(wh + 8 * j4);
            float4 v1 = *(const float4*)(wh + 8 * j4 + 4);
            uint4 pq = *(const uint4*)(rowp + 4 * j4);
            r0 = fmaf(bf_lo(pq.x), v0.x, r0); r1 = fmaf(bf_hi(pq.x), v0.y, r1);
            r2 = fmaf(bf_lo(pq.y), v0.z, r2); r3 = fmaf(bf_hi(pq.y), v0.w, r3);
            r0 = fmaf(bf_lo(pq.z), v1.x, r0); r1 = fmaf(bf_hi(pq.z), v1.y, r1);
            r2 = fmaf(bf_lo(pq.w), v1.z, r2); r3 = fmaf(bf_hi(pq.w), v1.w, r3);
        }
        rp[qq * 256 + ir] = (r0 + r1) + (r2 + r3);
    }
    __syncthreads();
    if (tid < 256) {
        float dot = (rp[tid] + rp[256 + tid]) + (rp[512 + tid] + rp[768 + tid]);
        float val = u[tid] * dot / log2f((float)(tid + 2));
        for (int o = 16; o; o >>= 1) val += __shfl_xor_sync(0xffffffffu, val, o);
        if (lane == 0) red[wid] = val;
    }
    __syncthreads();

    // ---- fused global reduction (atomic ticket; last CTA writes output) ----
    if (tid == 0) {
        float num = 0.f;
        for (int k = 0; k < 8; k++) num += red[k];
        bool valid = (idcg != 0.0f);
        float nd = valid ? (num / (idcg + 1e-10f)) : 0.0f;
        atomicAdd(&g_sum, nd);
        atomicAdd(&g_cnt, valid ? 1 : 0);
        __threadfence();
        unsigned tk = atomicAdd(&g_tk, 1u);
        if (tk == (unsigned)(B_DIM - 1)) {
            float sm = atomicAdd(&g_sum, 0.0f);
            int   c  = atomicAdd(&g_cnt, 0);
            out[0] = (c > 0) ? (-(sm / (float)c)) : 0.0f;
            g_sum = 0.f;
            g_cnt = 0;
            __threadfence();
            g_tk = 0u;
        }
    }
}

// ------------------------------------------------------------------ launch ---
extern "C" void kernel_launch(void* const* d_in, const int* in_sizes, int n_in,
                              void* d_out, int out_size) {
    const float* yp  = (const float*)d_in[0];
    const int*   ytr = (const int*)d_in[1];
    float*       out = (float*)d_out;

    size_t smem = (size_t)SMEM_WORDS * 4;   // 204032 B
    cudaFuncSetAttribute(mega_kernel, cudaFuncAttributeMaxDynamicSharedMemorySize, (int)smem);
    mega_kernel<<<B_DIM, NTHR, smem>>>(yp, ytr, out);
}

// round 12
// speedup vs baseline: 1.2404x; 1.2404x over previous
#include <cuda_runtime.h>
#include <cuda_bf16.h>

#define B_DIM 128
#define N_DIM 256
#define RSW   132                  // P row stride in words: even, %4==0 -> LDS.128 rows
#define ITERS 50
#define NTHR  512

// ---- smem word offsets ----
#define W_PH   0                       // 33792 : P bf16 padded rows (256 x 132)
#define W_S    33792
#define W_BM   34048
#define W_GA   34304
#define W_U    34560
#define W_V    34816
#define W_W    35072
#define W_SP   35328                   // 2048 : 8 x 256 column partials
#define W_RED  37376                   // 32
#define W_EI   37408                   // 256
#define W_PW   37664                   // 8*256 : r^k tables
#define W_AN   39712                   // 32*256 : anchor rows
#define SMEM_WORDS (W_AN + 32*256)     // 47904 words = 191616 B

__device__ float    g_sum = 0.f;
__device__ int      g_cnt = 0;
__device__ unsigned g_tk  = 0u;

__device__ __forceinline__ float bf_lo(unsigned w) { return __int_as_float(w << 16); }
__device__ __forceinline__ float bf_hi(unsigned w) { return __int_as_float(w & 0xffff0000u); }

// ------------------------------------------------------------- mega kernel ---
__global__ void __launch_bounds__(NTHR, 1)
mega_kernel(const float* __restrict__ yp, const int* __restrict__ ytr,
            float* __restrict__ out) {
    extern __shared__ unsigned smw[];
    unsigned* Pw = smw + W_PH;
    float* s   = (float*)(smw + W_S);
    float* Bm  = (float*)(smw + W_BM);
    float* gA  = (float*)(smw + W_GA);
    float* u   = (float*)(smw + W_U);
    float* v   = (float*)(smw + W_V);
    float* w   = (float*)(smw + W_W);
    float* sp  = (float*)(smw + W_SP);
    float* red = (float*)(smw + W_RED);
    int*   ei  = (int*)(smw + W_EI);
    float* pw  = (float*)(smw + W_PW);
    float* AN  = (float*)(smw + W_AN);

    const int tid  = threadIdx.x;
    const int b    = blockIdx.x;
    const int lane = tid & 31;
    const int wid  = tid >> 5;

    // ---- fused global min/max of y_true (L2-hot scan) ----
    int shift;
    {
        const int4* t4 = (const int4*)ytr;
        unsigned umx = 0u, umn = 0u;
        #pragma unroll
        for (int k = 0; k < (B_DIM * N_DIM / 4) / NTHR; k++) {
            int4 x = t4[tid + k * NTHR];
            unsigned u0 = (unsigned)x.x ^ 0x80000000u;
            unsigned u1 = (unsigned)x.y ^ 0x80000000u;
            unsigned u2 = (unsigned)x.z ^ 0x80000000u;
            unsigned u3 = (unsigned)x.w ^ 0x80000000u;
            umx = max(umx, max(max(u0, u1), max(u2, u3)));
            umn = max(umn, max(max(~u0, ~u1), max(~u2, ~u3)));
        }
        for (int o = 16; o; o >>= 1) {
            umx = max(umx, __shfl_xor_sync(0xffffffffu, umx, o));
            umn = max(umn, __shfl_xor_sync(0xffffffffu, umn, o));
        }
        unsigned* ur = (unsigned*)red;
        if (lane == 0) { ur[wid] = umx; ur[16 + wid] = umn; }
        __syncthreads();
        if (tid == 0) {
            for (int k = 1; k < 16; k++) { umx = max(umx, ur[k]); umn = max(umn, ur[16 + k]); }
            red[31] = __int_as_float((int)(umx ^ 0x80000000u) + (int)((~umn) ^ 0x80000000u));
        }
        __syncthreads();
        shift = __float_as_int(red[31]);
    }

    // ---- setup: scores, flipped relevancy, gains ----
    float sj = 0.f, gain = 0.f; int e = 0;
    if (tid < 256) {
        sj = yp[b * N_DIM + tid];
        s[tid] = sj;
        e = shift - ytr[b * N_DIM + tid];
        e = min(max(e, 0), 30);
        ei[tid] = e;
        gain = (float)((1u << e) - 1u);
        gA[tid] = gain;
        u[tid] = 1.0f;
    }
    __syncthreads();

    // ---- B_mat (Kahan) + IDCG via stable rank ----
    float idcg = 0.f;
    if (tid < 256) {
        float bsum = 0.f, bc = 0.f;
        int pos = 0;
        for (int k = 0; k < N_DIM; k++) {
            float d  = fabsf(sj - s[k]);
            float y  = d - bc;
            float t2 = bsum + y;
            bc = (t2 - bsum) - y;
            bsum = t2;
            int ek = ei[k];
            pos += (ek > e) ? 1 : 0;
            pos += ((k < tid) && (ek == e)) ? 1 : 0;
        }
        Bm[tid] = bsum;
        float x = gain / log2f((float)(pos + 2));
        for (int o = 16; o; o >>= 1) x += __shfl_xor_sync(0xffffffffu, x, o);
        if (lane == 0) red[wid] = x;
    }
    __syncthreads();
    if (tid == 0) { for (int k = 0; k < 8; k++) idcg += red[k]; }

    // ==== P build (exp-free block scheme) ====
    if (tid < 256) {
        float r = __expf(-2.0f * sj);
        float pk = 1.0f;
        pw[tid] = 1.0f;
        #pragma unroll
        for (int k = 1; k < 8; k++) { pk *= r; pw[k * 256 + tid] = pk; }
    }
    for (int m = wid; m < 32; m += 16) {
        float sc = (float)(255 - 16 * m);
        float lg[8];
        float mxl = -3.4e38f;
        #pragma unroll
        for (int c = 0; c < 8; c++) {
            int j = c * 32 + lane;
            lg[c] = fmaf(s[j], sc, -Bm[j]);
            mxl = fmaxf(mxl, lg[c]);
        }
        for (int o = 16; o; o >>= 1) mxl = fmaxf(mxl, __shfl_xor_sync(0xffffffffu, mxl, o));
        float* an = AN + m * 256;
        #pragma unroll
        for (int c = 0; c < 8; c++) an[c * 32 + lane] = __expf(lg[c] - mxl);
    }
    __syncthreads();

    // fill: warp per row; lane handles col pairs (64c+2lane, +1), c=0..3
    #pragma unroll 1
    for (int t = 0; t < 16; t++) {
        int i = wid + 16 * t;
        const float* an = AN + (i >> 3) * 256;
        const float* pk = pw + (i & 7) * 256;
        float f0[4], f1[4];
        float ssum = 0.f;
        #pragma unroll
        for (int c = 0; c < 4; c++) {
            float2 a2 = *(const float2*)(an + c * 64 + 2 * lane);
            float2 k2 = *(const float2*)(pk + c * 64 + 2 * lane);
            f0[c] = a2.x * k2.x;
            f1[c] = a2.y * k2.y;
            ssum += f0[c] + f1[c];
        }
        for (int o = 16; o; o >>= 1) ssum += __shfl_xor_sync(0xffffffffu, ssum, o);
        float inv = 1.0f / ssum;
        unsigned* row = Pw + (unsigned)i * RSW;
        #pragma unroll
        for (int c = 0; c < 4; c++) {
            __nv_bfloat162 pr = __floats2bfloat162_rn(f0[c] * inv, f1[c] * inv);
            row[c * 32 + lane] = *(unsigned*)&pr;
        }
    }
    __syncthreads();

    // ---- Sinkhorn with early exit (3 barriers/iter) ----
    const int o8 = tid >> 6;                         // row octant (32 rows)
    const int p4 = tid & 63;                         // column quad (cols 4p4..4p4+3)
    const unsigned* colp = Pw + (unsigned)(o8 * 32) * RSW + 2 * p4;
    const float* uo = u + o8 * 32;
    const unsigned* rowp = Pw + (unsigned)tid * RSW; // full row for tid < 256
    float vprev = 0.f;

    for (int it = 0; it < ITERS; it++) {
        // column pass: partial over 32 rows for cols 4p4..4p4+3 (LDS.64 on P)
        float a0 = 0.f, a1 = 0.f, a2 = 0.f, a3 = 0.f;
        #pragma unroll
        for (int ri = 0; ri < 8; ri++) {
            float4 uu = *(const float4*)(uo + 4 * ri);
            uint2 w0 = *(const uint2*)(colp + (4 * ri + 0) * RSW);
            uint2 w1 = *(const uint2*)(colp + (4 * ri + 1) * RSW);
            uint2 w2 = *(const uint2*)(colp + (4 * ri + 2) * RSW);
            uint2 w3 = *(const uint2*)(colp + (4 * ri + 3) * RSW);
            a0 = fmaf(bf_lo(w0.x), uu.x, a0); a1 = fmaf(bf_hi(w0.x), uu.x, a1);
            a2 = fmaf(bf_lo(w0.y), uu.x, a2); a3 = fmaf(bf_hi(w0.y), uu.x, a3);
            a0 = fmaf(bf_lo(w1.x), uu.y, a0); a1 = fmaf(bf_hi(w1.x), uu.y, a1);
            a2 = fmaf(bf_lo(w1.y), uu.y, a2); a3 = fmaf(bf_hi(w1.y), uu.y, a3);
            a0 = fmaf(bf_lo(w2.x), uu.z, a0); a1 = fmaf(bf_hi(w2.x), uu.z, a1);
            a2 = fmaf(bf_lo(w2.y), uu.z, a2); a3 = fmaf(bf_hi(w2.y), uu.z, a3);
            a0 = fmaf(bf_lo(w3.x), uu.w, a0); a1 = fmaf(bf_hi(w3.x), uu.w, a1);
            a2 = fmaf(bf_lo(w3.y), uu.w, a2); a3 = fmaf(bf_hi(w3.y), uu.w, a3);
        }
        *(float4*)(sp + o8 * 256 + 4 * p4) = make_float4(a0, a1, a2, a3);
        __syncthreads();

        // v update + convergence flag (threads 0..255)
        int ch = 0;
        if (tid < 256) {
            float S = ((sp[tid] + sp[256 + tid]) + (sp[512 + tid] + sp[768 + tid]))
                    + ((sp[1024 + tid] + sp[1280 + tid]) + (sp[1536 + tid] + sp[1792 + tid]));
            float vn = 1.0f / fmaxf(S, 1e-10f);
            v[tid] = vn;
            ch = (fabsf(vn - vprev) > 1e-4f * fabsf(vprev)) ? 1 : 0;
            vprev = vn;
        }
        if (__syncthreads_or(ch) == 0) break;

        // row pass: full-row dot with v (256 threads), u computed in-thread
        if (tid < 256) {
            float r0 = 0.f, r1 = 0.f, r2 = 0.f, r3 = 0.f;
            #pragma unroll
            for (int j4 = 0; j4 < 32; j4++) {
                float4 v0 = *(const float4*)(v + 8 * j4);
                float4 v1 = *(const float4*)(v + 8 * j4 + 4);
                uint4 pq = *(const uint4*)(rowp + 4 * j4);
                r0 = fmaf(bf_lo(pq.x), v0.x, r0); r1 = fmaf(bf_hi(pq.x), v0.y, r1);
                r2 = fmaf(bf_lo(pq.y), v0.z, r2); r3 = fmaf(bf_hi(pq.y), v0.w, r3);
                r0 = fmaf(bf_lo(pq.z), v1.x, r0); r1 = fmaf(bf_hi(pq.z), v1.y, r1);
                r2 = fmaf(bf_lo(pq.w), v1.z, r2); r3 = fmaf(bf_hi(pq.w), v1.w, r3);
            }
            u[tid] = 1.0f / fmaxf((r0 + r1) + (r2 + r3), 1e-10f);
        }
        __syncthreads();
    }

    // ---- final: num = sum_i disc_i * u_i * (P[i] . (v*g)) ----
    if (tid < 256) w[tid] = v[tid] * gA[tid];
    __syncthreads();
    if (tid < 256) {
        float r0 = 0.f, r1 = 0.f, r2 = 0.f, r3 = 0.f;
        #pragma unroll
        for (int j4 = 0; j4 < 32; j4++) {
            float4 v0 = *(const float4*)(w + 8 * j4);
            float4 v1 = *(const float4*)(w + 8 * j4 + 4);
            uint4 pq = *(const uint4*)(rowp + 4 * j4);
            r0 = fmaf(bf_lo(pq.x), v0.x, r0); r1 = fmaf(bf_hi(pq.x), v0.y, r1);
            r2 = fmaf(bf_lo(pq.y), v0.z, r2); r3 = fmaf(bf_hi(pq.y), v0.w, r3);
            r0 = fmaf(bf_lo(pq.z), v1.x, r0); r1 = fmaf(bf_hi(pq.z), v1.y, r1);
            r2 = fmaf(bf_lo(pq.w), v1.z, r2); r3 = fmaf(bf_hi(pq.w), v1.w, r3);
        }
        float dot = (r0 + r1) + (r2 + r3);
        float val = u[tid] * dot / log2f((float)(tid + 2));
        for (int o = 16; o; o >>= 1) val += __shfl_xor_sync(0xffffffffu, val, o);
        if (lane == 0) red[wid] = val;
    }
    __syncthreads();

    // ---- fused global reduction (atomic ticket; last CTA writes output) ----
    if (tid == 0) {
        float num = 0.f;
        for (int k = 0; k < 8; k++) num += red[k];
        bool valid = (idcg != 0.0f);
        float nd = valid ? (num / (idcg + 1e-10f)) : 0.0f;
        atomicAdd(&g_sum, nd);
        atomicAdd(&g_cnt, valid ? 1 : 0);
        __threadfence();
        unsigned tk = atomicAdd(&g_tk, 1u);
        if (tk == (unsigned)(B_DIM - 1)) {
            float sm = atomicAdd(&g_sum, 0.0f);
            int   c  = atomicAdd(&g_cnt, 0);
            out[0] = (c > 0) ? (-(sm / (float)c)) : 0.0f;
            g_sum = 0.f;
            g_cnt = 0;
            __threadfence();
            g_tk = 0u;
        }
    }
}

// ------------------------------------------------------------------ launch ---
extern "C" void kernel_launch(void* const* d_in, const int* in_sizes, int n_in,
                              void* d_out, int out_size) {
    const float* yp  = (const float*)d_in[0];
    const int*   ytr = (const int*)d_in[1];
    float*       out = (float*)d_out;

    size_t smem = (size_t)SMEM_WORDS * 4;   // 191616 B
    cudaFuncSetAttribute(mega_kernel, cudaFuncAttributeMaxDynamicSharedMemorySize, (int)smem);
    mega_kernel<<<B_DIM, NTHR, smem>>>(yp, ytr, out);
}